// round 1
// baseline (speedup 1.0000x reference)
#include <cuda_runtime.h>
#include <math.h>

// Problem constants (fixed by the dataset)
#define NMAX 100000
#define HID 256
#define H4  1024
#define GMAX 64

// ---------------- scratch (static device globals; no allocation) ----------------
__device__ float g_xcat[(size_t)NMAX * H4];   // concat of 4 branch outputs [N,1024]
__device__ float g_h[(size_t)NMAX * HID];     // GEMM output (h = x @ Wg)
__device__ float g_agg[(size_t)NMAX * HID];   // aggregation buffer / activations
__device__ float g_deg[NMAX];                 // degree -> dinv (in place)
__device__ float g_pooled[GMAX * HID];
__device__ float g_cnt[GMAX];
__device__ float g_head[GMAX * HID];

// ---------------- helpers ----------------
__device__ __forceinline__ void red_add_v4(float* addr, float4 v) {
    asm volatile("red.global.add.v4.f32 [%0], {%1,%2,%3,%4};"
                 :: "l"(addr), "f"(v.x), "f"(v.y), "f"(v.z), "f"(v.w)
                 : "memory");
}

// ---------------- GEMM: C[M x 256] = A[M x K] @ B[K x 256] (+bias, relu) --------
// BM=128, BN=64, BK=16, 256 threads, 8x4 per-thread tile.
__global__ __launch_bounds__(256)
void gemm_k(const float* __restrict__ A, const float* __restrict__ B,
            const float* __restrict__ bias, float* __restrict__ C,
            int M, int K, int ldc, int coff, int dorelu)
{
    __shared__ float As[16][128 + 4];
    __shared__ float Bs[16][64 + 4];
    const int t  = threadIdx.x;
    const int ty = t >> 4;       // 0..15 -> rows ty*8..ty*8+7
    const int tx = t & 15;       // 0..15 -> cols tx*4..tx*4+3
    const int row0 = blockIdx.y * 128;
    const int col0 = blockIdx.x * 64;

    float acc[8][4];
#pragma unroll
    for (int i = 0; i < 8; i++)
#pragma unroll
        for (int j = 0; j < 4; j++) acc[i][j] = 0.f;

    for (int k0 = 0; k0 < K; k0 += 16) {
        // Load A tile 128x16 (transposed into As[kk][r])
#pragma unroll
        for (int i = 0; i < 8; i++) {
            int li = t + i * 256;
            int r = li >> 4, kk = li & 15;
            int gr = row0 + r, gk = k0 + kk;
            float v = 0.f;
            if (gr < M && gk < K) v = A[(long)gr * K + gk];
            As[kk][r] = v;
        }
        // Load B tile 16x64
#pragma unroll
        for (int i = 0; i < 4; i++) {
            int li = t + i * 256;
            int kk = li >> 6, c = li & 63;
            int gk = k0 + kk;
            float v = 0.f;
            if (gk < K) v = B[(long)gk * 256 + col0 + c];
            Bs[kk][c] = v;
        }
        __syncthreads();
#pragma unroll
        for (int kk = 0; kk < 16; kk++) {
            float4 a0 = *(const float4*)&As[kk][ty * 8];
            float4 a1 = *(const float4*)&As[kk][ty * 8 + 4];
            float4 b  = *(const float4*)&Bs[kk][tx * 4];
            float av[8] = {a0.x, a0.y, a0.z, a0.w, a1.x, a1.y, a1.z, a1.w};
            float bv[4] = {b.x, b.y, b.z, b.w};
#pragma unroll
            for (int i = 0; i < 8; i++)
#pragma unroll
                for (int j = 0; j < 4; j++) acc[i][j] += av[i] * bv[j];
        }
        __syncthreads();
    }

    // Epilogue
    float4 bb = make_float4(0.f, 0.f, 0.f, 0.f);
    if (bias) bb = *(const float4*)&bias[col0 + tx * 4];
#pragma unroll
    for (int i = 0; i < 8; i++) {
        int gr = row0 + ty * 8 + i;
        if (gr >= M) continue;
        float4 v = make_float4(acc[i][0] + bb.x, acc[i][1] + bb.y,
                               acc[i][2] + bb.z, acc[i][3] + bb.w);
        if (dorelu) {
            v.x = fmaxf(v.x, 0.f); v.y = fmaxf(v.y, 0.f);
            v.z = fmaxf(v.z, 0.f); v.w = fmaxf(v.w, 0.f);
        }
        *(float4*)&C[(long)gr * ldc + coff + col0 + tx * 4] = v;
    }
}

// ---------------- degree / dinv ----------------
__global__ void deg_init_k(float* deg, int n) {
    int i = blockIdx.x * blockDim.x + threadIdx.x;
    if (i < n) deg[i] = 1.f;
}
__global__ void deg_acc_k(const int* __restrict__ dst, float* deg, int E) {
    int i = blockIdx.x * blockDim.x + threadIdx.x;
    if (i < E) atomicAdd(&deg[dst[i]], 1.f);
}
__global__ void dinv_k(float* deg, int n) {
    int i = blockIdx.x * blockDim.x + threadIdx.x;
    if (i < n) deg[i] = rsqrtf(deg[i]);
}

// ---------------- GCN aggregation ----------------
// init: agg = h * dinv^2 (self-loop term)
__global__ void selfloop_k(const float* __restrict__ h, const float* __restrict__ dinv,
                           float* __restrict__ agg, int n) {
    long i = (long)blockIdx.x * blockDim.x + threadIdx.x;
    if (i < (long)n * HID) {
        int node = (int)(i >> 8);
        float di = dinv[node];
        agg[i] = h[i] * di * di;
    }
}

// warp per edge: agg[dst] += h[src] * dinv[src]*dinv[dst]
__global__ __launch_bounds__(256)
void edge_agg_k(const float* __restrict__ h, const float* __restrict__ dinv,
                const int* __restrict__ src, const int* __restrict__ dst,
                float* __restrict__ agg, int E)
{
    int w = (int)(((long)blockIdx.x * blockDim.x + threadIdx.x) >> 5);
    int lane = threadIdx.x & 31;
    if (w >= E) return;
    int s = src[w], d = dst[w];
    float coef = dinv[s] * dinv[d];
    const float4* hs = (const float4*)(h + (size_t)s * HID);
    float* ad = agg + (size_t)d * HID;
    int b = lane * 2;                 // each lane: 8 contiguous floats = 2 float4
    float4 v0 = hs[b], v1 = hs[b + 1];
    v0.x *= coef; v0.y *= coef; v0.z *= coef; v0.w *= coef;
    v1.x *= coef; v1.y *= coef; v1.z *= coef; v1.w *= coef;
    red_add_v4(ad + b * 4, v0);
    red_add_v4(ad + b * 4 + 4, v1);
}

// x = relu(x + bias)
__global__ void bias_relu_k(float* __restrict__ x, const float* __restrict__ b, int n) {
    long i = (long)blockIdx.x * blockDim.x + threadIdx.x;
    if (i < (long)n * HID) x[i] = fmaxf(x[i] + b[i & 255], 0.f);
}

// ---------------- pooling ----------------
__global__ void pool_zero_k() {
    int i = blockIdx.x * blockDim.x + threadIdx.x;
    if (i < GMAX * HID) g_pooled[i] = 0.f;
    if (i < GMAX) g_cnt[i] = 0.f;
}
__global__ __launch_bounds__(256)
void pool_k(const float* __restrict__ x, const int* __restrict__ batch, int n) {
    int w = (int)(((long)blockIdx.x * blockDim.x + threadIdx.x) >> 5);
    int lane = threadIdx.x & 31;
    if (w >= n) return;
    int g = batch[w];
    if (lane == 0) atomicAdd(&g_cnt[g], 1.f);
    const float4* xs = (const float4*)(x + (size_t)w * HID);
    float* pd = g_pooled + (size_t)g * HID;
    int b = lane * 2;
    red_add_v4(pd + b * 4, xs[b]);
    red_add_v4(pd + b * 4 + 4, xs[b + 1]);
}
__global__ void pool_div_k() {
    int i = blockIdx.x * blockDim.x + threadIdx.x;
    if (i < GMAX * HID) g_pooled[i] /= fmaxf(g_cnt[i >> 8], 1.f);
}

// ---------------- head ----------------
__global__ __launch_bounds__(256)
void head1_k(const float* __restrict__ Wl1, const float* __restrict__ bl1) {
    __shared__ float sp[HID];
    int g = blockIdx.x, j = threadIdx.x;
    sp[j] = g_pooled[g * HID + j];
    __syncthreads();
    float acc = bl1[j];
#pragma unroll 8
    for (int k = 0; k < HID; k++) acc += sp[k] * Wl1[k * HID + j];
    g_head[g * HID + j] = fmaxf(acc, 0.f);
}
__global__ void head2_k(const float* __restrict__ Wl2, const float* __restrict__ bl2,
                        float* __restrict__ out) {
    int g = threadIdx.x;
    if (g >= GMAX) return;
    float l0 = bl2[0], l1 = bl2[1];
#pragma unroll 8
    for (int k = 0; k < HID; k++) {
        float v = g_head[g * HID + k];
        l0 += v * Wl2[k * 2];
        l1 += v * Wl2[k * 2 + 1];
    }
    float m = fmaxf(l0, l1);
    float lse = m + logf(expf(l0 - m) + expf(l1 - m));
    out[g * 2]     = l0 - lse;
    out[g * 2 + 1] = l1 - lse;
}

// ---------------- launch ----------------
extern "C" void kernel_launch(void* const* d_in, const int* in_sizes, int n_in,
                              void* d_out, int out_size)
{
    const float* content = (const float*)d_in[0];
    const float* bert    = (const float*)d_in[1];
    const float* profile = (const float*)d_in[2];
    const float* spacy   = (const float*)d_in[3];
    const int*   eidx    = (const int*)d_in[4];
    const int*   batch   = (const int*)d_in[5];
    const float* Wc  = (const float*)d_in[6],  *bc  = (const float*)d_in[7];
    const float* Wb  = (const float*)d_in[8],  *bb  = (const float*)d_in[9];
    const float* Wp  = (const float*)d_in[10], *bp  = (const float*)d_in[11];
    const float* Ws  = (const float*)d_in[12], *bs  = (const float*)d_in[13];
    const float* Wg1 = (const float*)d_in[14], *bg1 = (const float*)d_in[15];
    const float* Wg2 = (const float*)d_in[16], *bg2 = (const float*)d_in[17];
    const float* Wl1 = (const float*)d_in[18], *bl1 = (const float*)d_in[19];
    const float* Wl2 = (const float*)d_in[20], *bl2 = (const float*)d_in[21];

    const int N = in_sizes[5];       // batch vector length
    const int E = in_sizes[4] / 2;   // edge_index is [2, E]
    const int* src = eidx;
    const int* dst = eidx + E;

    float *xcat, *hbuf, *abuf, *deg;
    cudaGetSymbolAddress((void**)&xcat, g_xcat);
    cudaGetSymbolAddress((void**)&hbuf, g_h);
    cudaGetSymbolAddress((void**)&abuf, g_agg);
    cudaGetSymbolAddress((void**)&deg,  g_deg);

    const dim3 gemm_grid(4, (N + 127) / 128);   // 256 cols / 64, rows / 128
    const int  NT = 256;

    // degree -> dinv (in place in g_deg)
    deg_init_k<<<(N + NT - 1) / NT, NT>>>(deg, N);
    deg_acc_k<<<(E + NT - 1) / NT, NT>>>(dst, deg, E);
    dinv_k<<<(N + NT - 1) / NT, NT>>>(deg, N);

    // branch linears -> xcat [N, 1024]
    gemm_k<<<gemm_grid, NT>>>(content, Wc, bc, xcat, N, 310, H4, 0,   1);
    gemm_k<<<gemm_grid, NT>>>(bert,    Wb, bb, xcat, N, 768, H4, 256, 1);
    gemm_k<<<gemm_grid, NT>>>(profile, Wp, bp, xcat, N, 10,  H4, 512, 1);
    gemm_k<<<gemm_grid, NT>>>(spacy,   Ws, bs, xcat, N, 300, H4, 768, 1);

    // conv1: h = xcat @ Wg1
    gemm_k<<<gemm_grid, NT>>>(xcat, Wg1, nullptr, hbuf, N, H4, HID, 0, 0);
    selfloop_k<<<(int)(((long)N * HID + NT - 1) / NT), NT>>>(hbuf, deg, abuf, N);
    edge_agg_k<<<(E * 32 + NT - 1) / NT, NT>>>(hbuf, deg, src, dst, abuf, E);
    bias_relu_k<<<(int)(((long)N * HID + NT - 1) / NT), NT>>>(abuf, bg1, N);

    // conv2: h = x1 @ Wg2
    gemm_k<<<gemm_grid, NT>>>(abuf, Wg2, nullptr, hbuf, N, HID, HID, 0, 0);
    selfloop_k<<<(int)(((long)N * HID + NT - 1) / NT), NT>>>(hbuf, deg, abuf, N);
    edge_agg_k<<<(E * 32 + NT - 1) / NT, NT>>>(hbuf, deg, src, dst, abuf, E);
    bias_relu_k<<<(int)(((long)N * HID + NT - 1) / NT), NT>>>(abuf, bg2, N);

    // global mean pool
    pool_zero_k<<<(GMAX * HID + NT - 1) / NT, NT>>>();
    pool_k<<<(N * 32 + NT - 1) / NT, NT>>>(abuf, batch, N);
    pool_div_k<<<(GMAX * HID + NT - 1) / NT, NT>>>();

    // head
    head1_k<<<GMAX, HID>>>(Wl1, bl1);
    head2_k<<<1, 64>>>(Wl2, bl2, (float*)d_out);
}

// round 2
// speedup vs baseline: 2.9417x; 2.9417x over previous
#include <cuda_runtime.h>
#include <math.h>
#include <stdint.h>

// Problem constants (fixed by the dataset)
#define NMAX 100000
#define EMAX 1600000
#define HID 256
#define H4  1024
#define GMAX 64

// ---------------- scratch (static device globals; no allocation) ----------------
__device__ float g_xcat[(size_t)NMAX * H4];   // concat of 4 branch outputs [N,1024]
__device__ float g_h[(size_t)NMAX * HID];     // GEMM output (h = x @ Wg)
__device__ float g_agg[(size_t)NMAX * HID];   // aggregated activations
__device__ float g_dinv[NMAX];                // 1/sqrt(deg)
__device__ int   g_cnt_i[NMAX];               // edge count per dst
__device__ int   g_off[NMAX + 1];             // CSR offsets
__device__ int   g_cursor[NMAX];              // scatter cursors
__device__ int   g_bsum[256];                 // scan block sums
__device__ int   g_csr[EMAX];                 // CSR src indices
__device__ float g_pooled[GMAX * HID];
__device__ float g_cntf[GMAX];
__device__ float g_head[GMAX * HID];

// ---------------- helpers ----------------
__device__ __forceinline__ void red_add_v4(float* addr, float4 v) {
    asm volatile("red.global.add.v4.f32 [%0], {%1,%2,%3,%4};"
                 :: "l"(addr), "f"(v.x), "f"(v.y), "f"(v.z), "f"(v.w)
                 : "memory");
}
__device__ __forceinline__ uint32_t f2tf32(float f) {
    uint32_t u;
    asm("cvt.rna.tf32.f32 %0, %1;" : "=r"(u) : "f"(f));
    return u;
}
__device__ __forceinline__ void mma_tf32(float c[4], uint32_t a[4], uint32_t b[2]) {
    asm volatile(
        "mma.sync.aligned.m16n8k8.row.col.f32.tf32.tf32.f32 "
        "{%0,%1,%2,%3}, {%4,%5,%6,%7}, {%8,%9}, {%0,%1,%2,%3};"
        : "+f"(c[0]), "+f"(c[1]), "+f"(c[2]), "+f"(c[3])
        : "r"(a[0]), "r"(a[1]), "r"(a[2]), "r"(a[3]), "r"(b[0]), "r"(b[1]));
}

// ---------------- TF32 tensor-core GEMM ----------------
// C[M x 256] = A[M x K] @ B[K x 256] (+bias, relu), BM=128 BN=128 BK=32.
// 8 warps as 2x4; warp tile 64x32; mma m16n8k8 tf32.
#define BM 128
#define BN 128
#define BK 32

__global__ __launch_bounds__(256, 2)
void gemm_tf32_k(const float* __restrict__ A, const float* __restrict__ B,
                 const float* __restrict__ bias, float* __restrict__ C,
                 int M, int K, int ldc, int coff, int dorelu)
{
    __shared__ float As[BM][BK + 4];   // stride 36: (36*g)%32=4g -> conflict-free frag reads
    __shared__ float Bs[BK][BN + 8];   // stride 136: (136*tig)%32=8tig -> conflict-free

    const int t = threadIdx.x;
    const int lane = t & 31, warp = t >> 5;
    const int wr = warp >> 2, wc = warp & 3;   // 2 x 4 warp grid
    const int g = lane >> 2, tig = lane & 3;
    const int row0 = blockIdx.y * BM;
    const int col0 = blockIdx.x * BN;
    const int mW = wr * 64, nW = wc * 32;

    float c[4][4][4];
#pragma unroll
    for (int i = 0; i < 4; i++)
#pragma unroll
        for (int j = 0; j < 4; j++)
#pragma unroll
            for (int r = 0; r < 4; r++) c[i][j][r] = 0.f;

    const int kTiles = (K + BK - 1) / BK;
    for (int kt = 0; kt < kTiles; kt++) {
        const int k0 = kt * BK;
        // Load A tile 128x32 (scalar; rows may be unaligned for odd K)
#pragma unroll
        for (int i = 0; i < 16; i++) {
            int li = t + i * 256;
            int kk = li & 31, m = li >> 5;
            int gr = row0 + m, gk = k0 + kk;
            float v = 0.f;
            if (gr < M && gk < K) v = A[(size_t)gr * K + gk];
            As[m][kk] = __uint_as_float(f2tf32(v));
        }
        // Load B tile 32x128 (vectorized; B rows are 256-float aligned)
#pragma unroll
        for (int i = 0; i < 4; i++) {
            int li = t + i * 256;          // float4 index
            int n4 = (li & 31) * 4;
            int kk = li >> 5;
            int gk = k0 + kk;
            float4 v = make_float4(0.f, 0.f, 0.f, 0.f);
            if (gk < K) v = *(const float4*)&B[(size_t)gk * 256 + col0 + n4];
            float4 w;
            w.x = __uint_as_float(f2tf32(v.x));
            w.y = __uint_as_float(f2tf32(v.y));
            w.z = __uint_as_float(f2tf32(v.z));
            w.w = __uint_as_float(f2tf32(v.w));
            *(float4*)&Bs[kk][n4] = w;     // row stride 136 floats = 544B, 16B-aligned
        }
        __syncthreads();

#pragma unroll
        for (int ks = 0; ks < 4; ks++) {
            uint32_t a[4][4], b[4][2];
#pragma unroll
            for (int mt = 0; mt < 4; mt++) {
                int mr = mW + mt * 16 + g;
                a[mt][0] = __float_as_uint(As[mr][ks * 8 + tig]);
                a[mt][1] = __float_as_uint(As[mr + 8][ks * 8 + tig]);
                a[mt][2] = __float_as_uint(As[mr][ks * 8 + tig + 4]);
                a[mt][3] = __float_as_uint(As[mr + 8][ks * 8 + tig + 4]);
            }
#pragma unroll
            for (int nt = 0; nt < 4; nt++) {
                int nc = nW + nt * 8 + g;
                b[nt][0] = __float_as_uint(Bs[ks * 8 + tig][nc]);
                b[nt][1] = __float_as_uint(Bs[ks * 8 + tig + 4][nc]);
            }
#pragma unroll
            for (int mt = 0; mt < 4; mt++)
#pragma unroll
                for (int nt = 0; nt < 4; nt++)
                    mma_tf32(c[mt][nt], a[mt], b[nt]);
        }
        __syncthreads();
    }

    // Epilogue: each thread owns (row g/g+8, cols tig*2, tig*2+1) per tile
#pragma unroll
    for (int nt = 0; nt < 4; nt++) {
        int colg = nW + nt * 8 + tig * 2;                     // col within 0..255 block? (BN=128)
        int col = col0 + colg;                                // global col 0..255
        float b0 = 0.f, b1 = 0.f;
        if (bias) { b0 = bias[col]; b1 = bias[col + 1]; }
#pragma unroll
        for (int mt = 0; mt < 4; mt++) {
            int r0 = row0 + mW + mt * 16 + g;
#pragma unroll
            for (int half = 0; half < 2; half++) {
                int gr = r0 + half * 8;
                if (gr >= M) continue;
                float v0 = c[mt][nt][half * 2 + 0] + b0;
                float v1 = c[mt][nt][half * 2 + 1] + b1;
                if (dorelu) { v0 = fmaxf(v0, 0.f); v1 = fmaxf(v1, 0.f); }
                float2 vv = make_float2(v0, v1);
                *(float2*)&C[(size_t)gr * ldc + coff + col] = vv;
            }
        }
    }
}

// ---------------- degree / CSR build ----------------
__global__ void zero_cnt_k(int n) {
    int i = blockIdx.x * blockDim.x + threadIdx.x;
    if (i < n) g_cnt_i[i] = 0;
}
__global__ void hist_k(const int* __restrict__ dst, int E) {
    int i = blockIdx.x * blockDim.x + threadIdx.x;
    if (i < E) atomicAdd(&g_cnt_i[dst[i]], 1);
}
__global__ void dinv_k(int n) {
    int i = blockIdx.x * blockDim.x + threadIdx.x;
    if (i < n) g_dinv[i] = rsqrtf(1.0f + (float)g_cnt_i[i]);
}
// scan1: each block scans 1024 counts (256 thr x 4)
__global__ __launch_bounds__(256)
void scan1_k(int n) {
    __shared__ int sh[256];
    int b = blockIdx.x, t = threadIdx.x;
    int base = b * 1024 + t * 4;
    int v0 = (base + 0 < n) ? g_cnt_i[base + 0] : 0;
    int v1 = (base + 1 < n) ? g_cnt_i[base + 1] : 0;
    int v2 = (base + 2 < n) ? g_cnt_i[base + 2] : 0;
    int v3 = (base + 3 < n) ? g_cnt_i[base + 3] : 0;
    int sum = v0 + v1 + v2 + v3;
    sh[t] = sum;
    __syncthreads();
    for (int ofs = 1; ofs < 256; ofs <<= 1) {
        int x = (t >= ofs) ? sh[t - ofs] : 0;
        __syncthreads();
        sh[t] += x;
        __syncthreads();
    }
    int excl = sh[t] - sum;
    if (base + 0 < n) g_off[base + 0] = excl;
    if (base + 1 < n) g_off[base + 1] = excl + v0;
    if (base + 2 < n) g_off[base + 2] = excl + v0 + v1;
    if (base + 3 < n) g_off[base + 3] = excl + v0 + v1 + v2;
    if (t == 255) g_bsum[b] = sh[255];
}
__global__ __launch_bounds__(256)
void scan2_k(int nb) {
    __shared__ int sh[256];
    int t = threadIdx.x;
    int orig = (t < nb) ? g_bsum[t] : 0;
    sh[t] = orig;
    __syncthreads();
    for (int ofs = 1; ofs < 256; ofs <<= 1) {
        int x = (t >= ofs) ? sh[t - ofs] : 0;
        __syncthreads();
        sh[t] += x;
        __syncthreads();
    }
    g_bsum[t] = sh[t] - orig;   // exclusive
}
__global__ void scan3_k(int n, int E) {
    int i = blockIdx.x * blockDim.x + threadIdx.x;
    if (i < n) {
        int o = g_off[i] + g_bsum[i >> 10];
        g_off[i] = o;
        g_cursor[i] = o;
    }
    if (i == 0) g_off[n] = E;
}
__global__ void scatter_k(const int* __restrict__ src, const int* __restrict__ dst, int E) {
    int e = blockIdx.x * blockDim.x + threadIdx.x;
    if (e < E) {
        int d = dst[e];
        int p = atomicAdd(&g_cursor[d], 1);
        g_csr[p] = src[e];
    }
}

// ---------------- fused GCN aggregation: self-loop + gather + bias + relu -------
// one warp per dst node; lane owns 8 contiguous floats (2 float4)
__global__ __launch_bounds__(256)
void gcn_agg_k(const float* __restrict__ h, const float* __restrict__ bias,
               float* __restrict__ out, int n)
{
    int w = (int)(((long)blockIdx.x * blockDim.x + threadIdx.x) >> 5);
    int lane = threadIdx.x & 31;
    if (w >= n) return;
    const float din = g_dinv[w];
    const float4* hv = (const float4*)h;
    const size_t fb = (size_t)w * 64 + lane * 2;

    float4 s0 = hv[fb], s1 = hv[fb + 1];
    float sc = din * din;
    float4 acc0 = make_float4(s0.x * sc, s0.y * sc, s0.z * sc, s0.w * sc);
    float4 acc1 = make_float4(s1.x * sc, s1.y * sc, s1.z * sc, s1.w * sc);

    int e = g_off[w], end = g_off[w + 1];
    for (; e + 2 <= end; e += 2) {
        int sA = g_csr[e], sB = g_csr[e + 1];
        float cA = g_dinv[sA] * din, cB = g_dinv[sB] * din;
        size_t bA = (size_t)sA * 64 + lane * 2;
        size_t bB = (size_t)sB * 64 + lane * 2;
        float4 a0 = hv[bA], a1 = hv[bA + 1];
        float4 b0 = hv[bB], b1 = hv[bB + 1];
        acc0.x += a0.x * cA + b0.x * cB;  acc0.y += a0.y * cA + b0.y * cB;
        acc0.z += a0.z * cA + b0.z * cB;  acc0.w += a0.w * cA + b0.w * cB;
        acc1.x += a1.x * cA + b1.x * cB;  acc1.y += a1.y * cA + b1.y * cB;
        acc1.z += a1.z * cA + b1.z * cB;  acc1.w += a1.w * cA + b1.w * cB;
    }
    if (e < end) {
        int sA = g_csr[e];
        float cA = g_dinv[sA] * din;
        size_t bA = (size_t)sA * 64 + lane * 2;
        float4 a0 = hv[bA], a1 = hv[bA + 1];
        acc0.x += a0.x * cA; acc0.y += a0.y * cA; acc0.z += a0.z * cA; acc0.w += a0.w * cA;
        acc1.x += a1.x * cA; acc1.y += a1.y * cA; acc1.z += a1.z * cA; acc1.w += a1.w * cA;
    }
    const float4* bv = (const float4*)bias;
    float4 bb0 = bv[lane * 2], bb1 = bv[lane * 2 + 1];
    acc0.x = fmaxf(acc0.x + bb0.x, 0.f); acc0.y = fmaxf(acc0.y + bb0.y, 0.f);
    acc0.z = fmaxf(acc0.z + bb0.z, 0.f); acc0.w = fmaxf(acc0.w + bb0.w, 0.f);
    acc1.x = fmaxf(acc1.x + bb1.x, 0.f); acc1.y = fmaxf(acc1.y + bb1.y, 0.f);
    acc1.z = fmaxf(acc1.z + bb1.z, 0.f); acc1.w = fmaxf(acc1.w + bb1.w, 0.f);
    float4* ov = (float4*)out;
    ov[fb] = acc0;
    ov[fb + 1] = acc1;
}

// ---------------- pooling ----------------
__global__ void pool_zero_k() {
    int i = blockIdx.x * blockDim.x + threadIdx.x;
    if (i < GMAX * HID) g_pooled[i] = 0.f;
    if (i < GMAX) g_cntf[i] = 0.f;
}
__global__ __launch_bounds__(256)
void pool_k(const float* __restrict__ x, const int* __restrict__ batch, int n) {
    int w = (int)(((long)blockIdx.x * blockDim.x + threadIdx.x) >> 5);
    int lane = threadIdx.x & 31;
    if (w >= n) return;
    int gidx = batch[w];
    if (lane == 0) atomicAdd(&g_cntf[gidx], 1.f);
    const float4* xs = (const float4*)(x + (size_t)w * HID);
    float* pd = g_pooled + (size_t)gidx * HID;
    int b = lane * 2;
    red_add_v4(pd + b * 4, xs[b]);
    red_add_v4(pd + b * 4 + 4, xs[b + 1]);
}
__global__ void pool_div_k() {
    int i = blockIdx.x * blockDim.x + threadIdx.x;
    if (i < GMAX * HID) g_pooled[i] /= fmaxf(g_cntf[i >> 8], 1.f);
}

// ---------------- head ----------------
__global__ __launch_bounds__(256)
void head1_k(const float* __restrict__ Wl1, const float* __restrict__ bl1) {
    __shared__ float sp[HID];
    int g = blockIdx.x, j = threadIdx.x;
    sp[j] = g_pooled[g * HID + j];
    __syncthreads();
    float acc = bl1[j];
#pragma unroll 8
    for (int k = 0; k < HID; k++) acc += sp[k] * Wl1[k * HID + j];
    g_head[g * HID + j] = fmaxf(acc, 0.f);
}
__global__ void head2_k(const float* __restrict__ Wl2, const float* __restrict__ bl2,
                        float* __restrict__ out) {
    int g = threadIdx.x;
    if (g >= GMAX) return;
    float l0 = bl2[0], l1 = bl2[1];
#pragma unroll 8
    for (int k = 0; k < HID; k++) {
        float v = g_head[g * HID + k];
        l0 += v * Wl2[k * 2];
        l1 += v * Wl2[k * 2 + 1];
    }
    float m = fmaxf(l0, l1);
    float lse = m + logf(expf(l0 - m) + expf(l1 - m));
    out[g * 2]     = l0 - lse;
    out[g * 2 + 1] = l1 - lse;
}

// ---------------- launch ----------------
extern "C" void kernel_launch(void* const* d_in, const int* in_sizes, int n_in,
                              void* d_out, int out_size)
{
    const float* content = (const float*)d_in[0];
    const float* bert    = (const float*)d_in[1];
    const float* profile = (const float*)d_in[2];
    const float* spacy   = (const float*)d_in[3];
    const int*   eidx    = (const int*)d_in[4];
    const int*   batch   = (const int*)d_in[5];
    const float* Wc  = (const float*)d_in[6],  *bc  = (const float*)d_in[7];
    const float* Wb  = (const float*)d_in[8],  *bb  = (const float*)d_in[9];
    const float* Wp  = (const float*)d_in[10], *bp  = (const float*)d_in[11];
    const float* Ws  = (const float*)d_in[12], *bs  = (const float*)d_in[13];
    const float* Wg1 = (const float*)d_in[14], *bg1 = (const float*)d_in[15];
    const float* Wg2 = (const float*)d_in[16], *bg2 = (const float*)d_in[17];
    const float* Wl1 = (const float*)d_in[18], *bl1 = (const float*)d_in[19];
    const float* Wl2 = (const float*)d_in[20], *bl2 = (const float*)d_in[21];

    const int N = in_sizes[5];
    const int E = in_sizes[4] / 2;
    const int* src = eidx;
    const int* dst = eidx + E;

    float *xcat, *hbuf, *abuf;
    cudaGetSymbolAddress((void**)&xcat, g_xcat);
    cudaGetSymbolAddress((void**)&hbuf, g_h);
    cudaGetSymbolAddress((void**)&abuf, g_agg);

    const int NT = 256;
    const dim3 gg(2, (N + BM - 1) / BM);  // 256 cols / 128
    const int nb = (N + 1023) / 1024;

    // CSR + dinv
    zero_cnt_k<<<(N + NT - 1) / NT, NT>>>(N);
    hist_k<<<(E + NT - 1) / NT, NT>>>(dst, E);
    dinv_k<<<(N + NT - 1) / NT, NT>>>(N);
    scan1_k<<<nb, NT>>>(N);
    scan2_k<<<1, NT>>>(nb);
    scan3_k<<<(N + NT - 1) / NT, NT>>>(N, E);
    scatter_k<<<(E + NT - 1) / NT, NT>>>(src, dst, E);

    // branch linears -> xcat [N, 1024]
    gemm_tf32_k<<<gg, NT>>>(content, Wc, bc, xcat, N, 310, H4, 0,   1);
    gemm_tf32_k<<<gg, NT>>>(bert,    Wb, bb, xcat, N, 768, H4, 256, 1);
    gemm_tf32_k<<<gg, NT>>>(profile, Wp, bp, xcat, N, 10,  H4, 512, 1);
    gemm_tf32_k<<<gg, NT>>>(spacy,   Ws, bs, xcat, N, 300, H4, 768, 1);

    // conv1
    gemm_tf32_k<<<gg, NT>>>(xcat, Wg1, nullptr, hbuf, N, H4, HID, 0, 0);
    gcn_agg_k<<<(N * 32 + NT - 1) / NT, NT>>>(hbuf, bg1, abuf, N);

    // conv2
    gemm_tf32_k<<<gg, NT>>>(abuf, Wg2, nullptr, hbuf, N, HID, HID, 0, 0);
    gcn_agg_k<<<(N * 32 + NT - 1) / NT, NT>>>(hbuf, bg2, abuf, N);

    // global mean pool
    pool_zero_k<<<(GMAX * HID + NT - 1) / NT, NT>>>();
    pool_k<<<(N * 32 + NT - 1) / NT, NT>>>(abuf, batch, N);
    pool_div_k<<<(GMAX * HID + NT - 1) / NT, NT>>>();

    // head
    head1_k<<<GMAX, HID>>>(Wl1, bl1);
    head2_k<<<1, 64>>>(Wl2, bl2, (float*)d_out);
}

// round 7
// speedup vs baseline: 3.9896x; 1.3562x over previous
#include <cuda_runtime.h>
#include <cuda_fp16.h>
#include <math.h>
#include <stdint.h>

#define NMAX 100000
#define EMAX 1600000
#define HID 256
#define H4  1024
#define GMAX 64

// ---------------- scratch (static device globals; no allocation) ----------------
__device__ float  g_xcat[(size_t)NMAX * H4];   // concat of branch outputs [N,1024]
__device__ float  g_agg[(size_t)NMAX * HID];   // aggregated activations (fp32)
__device__ __half g_hh[(size_t)NMAX * HID];    // h * dinv[row], fp16 (gather payload)
__device__ float  g_dinv[NMAX];
__device__ int    g_cnt_i[NMAX];
__device__ int    g_off[NMAX + 1];
__device__ int    g_cursor[NMAX];
__device__ int    g_bsum[256];
__device__ int    g_csr[EMAX];
__device__ float  g_pooled[GMAX * HID];
__device__ float  g_cntf[GMAX];
__device__ float  g_head[GMAX * HID];

// ---------------- helpers ----------------
__device__ __forceinline__ void red_add_v4(float* addr, float4 v) {
    asm volatile("red.global.add.v4.f32 [%0], {%1,%2,%3,%4};"
                 :: "l"(addr), "f"(v.x), "f"(v.y), "f"(v.z), "f"(v.w)
                 : "memory");
}
__device__ __forceinline__ void mma_tf32(float c[4], uint32_t a[4], uint32_t b[2]) {
    asm volatile(
        "mma.sync.aligned.m16n8k8.row.col.f32.tf32.tf32.f32 "
        "{%0,%1,%2,%3}, {%4,%5,%6,%7}, {%8,%9}, {%0,%1,%2,%3};"
        : "+f"(c[0]), "+f"(c[1]), "+f"(c[2]), "+f"(c[3])
        : "r"(a[0]), "r"(a[1]), "r"(a[2]), "r"(a[3]), "r"(b[0]), "r"(b[1]));
}
__device__ __forceinline__ void cpa4(uint32_t d, const float* s, int nbytes) {
    asm volatile("cp.async.ca.shared.global [%0], [%1], 4, %2;"
                 :: "r"(d), "l"(s), "r"(nbytes) : "memory");
}
__device__ __forceinline__ void cpa16(uint32_t d, const float* s, int nbytes) {
    asm volatile("cp.async.cg.shared.global [%0], [%1], 16, %2;"
                 :: "r"(d), "l"(s), "r"(nbytes) : "memory");
}
#define CP_COMMIT() asm volatile("cp.async.commit_group;" ::: "memory")

// ---------------- TF32 tensor-core GEMM, cp.async 2-stage pipeline ----------------
// C[M x 256] = A[M x K] @ B[K x 256]; BM=128 BN=128 BK=32; 8 warps (2x4), 64x32/warp.
#define BM 128
#define BN 128
#define BK 32
#define AS_LD 36            // As row stride (bank-conflict-free frag loads)
#define BS_LD 136           // Bs row stride
#define AS_SZ (BM * AS_LD)  // one stage
#define BS_SZ (BK * BS_LD)
#define GEMM_SMEM ((2 * AS_SZ + 2 * BS_SZ) * 4)

__global__ __launch_bounds__(256, 2)
void gemm_tf32_k(const float* __restrict__ A, const float* __restrict__ B,
                 const float* __restrict__ bias, float* __restrict__ C,
                 __half* __restrict__ Ch, const float* __restrict__ dscale,
                 int M, int K, int ldc, int coff, int dorelu)
{
    extern __shared__ float sm[];
    float* Asm = sm;                 // [2][BM][AS_LD]
    float* Bsm = sm + 2 * AS_SZ;     // [2][BK][BS_LD]

    const int t = threadIdx.x;
    const int lane = t & 31, warp = t >> 5;
    const int wr = warp >> 2, wc = warp & 3;
    const int g = lane >> 2, tig = lane & 3;
    const int row0 = blockIdx.y * BM;
    const int col0 = blockIdx.x * BN;
    const int mW = wr * 64, nW = wc * 32;
    const bool k4 = (K & 3) == 0;

    float c[4][4][4];
#pragma unroll
    for (int i = 0; i < 4; i++)
#pragma unroll
        for (int j = 0; j < 4; j++)
#pragma unroll
            for (int r = 0; r < 4; r++) c[i][j][r] = 0.f;

    const int kTiles = (K + BK - 1) / BK;

    // tile loader (cp.async into stage st)
    auto load_tile = [&](int kt, int st) {
        const int k0 = kt * BK;
        float* As = Asm + st * AS_SZ;
        float* Bs = Bsm + st * BS_SZ;
        if (k4) {
            // A: 128x32 = 1024 float4, 4 per thread
#pragma unroll
            for (int i = 0; i < 4; i++) {
                int li = t + i * 256;
                int m = li >> 3, kk4 = (li & 7) * 4;
                int gr = row0 + m, gk = k0 + kk4;
                int nb = (gr < M && gk < K) ? 16 : 0;
                int grc = gr < M ? gr : M - 1;
                int gkc = gk < K ? gk : 0;
                uint32_t d = (uint32_t)__cvta_generic_to_shared(&As[m * AS_LD + kk4]);
                cpa16(d, &A[(size_t)grc * K + gkc], nb);
            }
        } else {
#pragma unroll
            for (int i = 0; i < 16; i++) {
                int li = t + i * 256;
                int kk = li & 31, m = li >> 5;
                int gr = row0 + m, gk = k0 + kk;
                int nb = (gr < M && gk < K) ? 4 : 0;
                int grc = gr < M ? gr : M - 1;
                int gkc = gk < K ? gk : 0;
                uint32_t d = (uint32_t)__cvta_generic_to_shared(&As[m * AS_LD + kk]);
                cpa4(d, &A[(size_t)grc * K + gkc], nb);
            }
        }
        // B: 32x128 = 1024 float4, 4 per thread (B rows 256-float aligned)
#pragma unroll
        for (int i = 0; i < 4; i++) {
            int li = t + i * 256;
            int n4 = (li & 31) * 4;
            int kk = li >> 5;
            int gk = k0 + kk;
            int nb = (gk < K) ? 16 : 0;
            int gkc = gk < K ? gk : 0;
            uint32_t d = (uint32_t)__cvta_generic_to_shared(&Bs[kk * BS_LD + n4]);
            cpa16(d, &B[(size_t)gkc * 256 + col0 + n4], nb);
        }
        CP_COMMIT();
    };

    load_tile(0, 0);

    for (int kt = 0; kt < kTiles; kt++) {
        const int cur = kt & 1;
        if (kt + 1 < kTiles) {
            load_tile(kt + 1, (kt + 1) & 1);
            asm volatile("cp.async.wait_group 1;" ::: "memory");
        } else {
            asm volatile("cp.async.wait_group 0;" ::: "memory");
        }
        __syncthreads();

        const float* As = Asm + cur * AS_SZ;
        const float* Bs = Bsm + cur * BS_SZ;
#pragma unroll
        for (int ks = 0; ks < 4; ks++) {
            uint32_t a[4][4], b[4][2];
#pragma unroll
            for (int mt = 0; mt < 4; mt++) {
                int mr = mW + mt * 16 + g;
                a[mt][0] = __float_as_uint(As[mr * AS_LD + ks * 8 + tig]);
                a[mt][1] = __float_as_uint(As[(mr + 8) * AS_LD + ks * 8 + tig]);
                a[mt][2] = __float_as_uint(As[mr * AS_LD + ks * 8 + tig + 4]);
                a[mt][3] = __float_as_uint(As[(mr + 8) * AS_LD + ks * 8 + tig + 4]);
            }
#pragma unroll
            for (int nt = 0; nt < 4; nt++) {
                int nc = nW + nt * 8 + g;
                b[nt][0] = __float_as_uint(Bs[(ks * 8 + tig) * BS_LD + nc]);
                b[nt][1] = __float_as_uint(Bs[(ks * 8 + tig + 4) * BS_LD + nc]);
            }
#pragma unroll
            for (int mt = 0; mt < 4; mt++)
#pragma unroll
                for (int nt = 0; nt < 4; nt++)
                    mma_tf32(c[mt][nt], a[mt], b[nt]);
        }
        __syncthreads();
    }

    // Epilogue
#pragma unroll
    for (int nt = 0; nt < 4; nt++) {
        int col = col0 + nW + nt * 8 + tig * 2;
        float b0 = 0.f, b1 = 0.f;
        if (bias) { b0 = bias[col]; b1 = bias[col + 1]; }
#pragma unroll
        for (int mt = 0; mt < 4; mt++) {
            int r0 = row0 + mW + mt * 16 + g;
#pragma unroll
            for (int half = 0; half < 2; half++) {
                int gr = r0 + half * 8;
                if (gr >= M) continue;
                float v0 = c[mt][nt][half * 2 + 0] + b0;
                float v1 = c[mt][nt][half * 2 + 1] + b1;
                if (Ch) {
                    float sc = dscale[gr];
                    __half2 hv = __floats2half2_rn(v0 * sc, v1 * sc);
                    *(__half2*)&Ch[(size_t)gr * 256 + col] = hv;
                } else {
                    if (dorelu) { v0 = fmaxf(v0, 0.f); v1 = fmaxf(v1, 0.f); }
                    *(float2*)&C[(size_t)gr * ldc + coff + col] = make_float2(v0, v1);
                }
            }
        }
    }
}

// ---------------- degree / CSR build ----------------
__global__ void zero_cnt_k(int n) {
    int i = blockIdx.x * blockDim.x + threadIdx.x;
    if (i < n) g_cnt_i[i] = 0;
}
__global__ void hist_k(const int* __restrict__ dst, int E) {
    int i = blockIdx.x * blockDim.x + threadIdx.x;
    if (i < E) atomicAdd(&g_cnt_i[dst[i]], 1);
}
__global__ void dinv_k(int n) {
    int i = blockIdx.x * blockDim.x + threadIdx.x;
    if (i < n) g_dinv[i] = rsqrtf(1.0f + (float)g_cnt_i[i]);
}
__global__ __launch_bounds__(256)
void scan1_k(int n) {
    __shared__ int sh[256];
    int b = blockIdx.x, t = threadIdx.x;
    int base = b * 1024 + t * 4;
    int v0 = (base + 0 < n) ? g_cnt_i[base + 0] : 0;
    int v1 = (base + 1 < n) ? g_cnt_i[base + 1] : 0;
    int v2 = (base + 2 < n) ? g_cnt_i[base + 2] : 0;
    int v3 = (base + 3 < n) ? g_cnt_i[base + 3] : 0;
    int sum = v0 + v1 + v2 + v3;
    sh[t] = sum;
    __syncthreads();
    for (int ofs = 1; ofs < 256; ofs <<= 1) {
        int x = (t >= ofs) ? sh[t - ofs] : 0;
        __syncthreads();
        sh[t] += x;
        __syncthreads();
    }
    int excl = sh[t] - sum;
    if (base + 0 < n) g_off[base + 0] = excl;
    if (base + 1 < n) g_off[base + 1] = excl + v0;
    if (base + 2 < n) g_off[base + 2] = excl + v0 + v1;
    if (base + 3 < n) g_off[base + 3] = excl + v0 + v1 + v2;
    if (t == 255) g_bsum[b] = sh[255];
}
__global__ __launch_bounds__(256)
void scan2_k(int nb) {
    __shared__ int sh[256];
    int t = threadIdx.x;
    int orig = (t < nb) ? g_bsum[t] : 0;
    sh[t] = orig;
    __syncthreads();
    for (int ofs = 1; ofs < 256; ofs <<= 1) {
        int x = (t >= ofs) ? sh[t - ofs] : 0;
        __syncthreads();
        sh[t] += x;
        __syncthreads();
    }
    g_bsum[t] = sh[t] - orig;
}
__global__ void scan3_k(int n, int E) {
    int i = blockIdx.x * blockDim.x + threadIdx.x;
    if (i < n) {
        int o = g_off[i] + g_bsum[i >> 10];
        g_off[i] = o;
        g_cursor[i] = o;
    }
    if (i == 0) g_off[n] = E;
}
__global__ void scatter_k(const int* __restrict__ src, const int* __restrict__ dst, int E) {
    int e = blockIdx.x * blockDim.x + threadIdx.x;
    if (e < E) {
        int d = dst[e];
        int p = atomicAdd(&g_cursor[d], 1);
        g_csr[p] = src[e];
    }
}

// ---------------- fused GCN aggregation (fp16 gather) ----------------
// hs[i] = h[i]*dinv[i] (fp16). out[d] = relu(dinv[d]*(sum_nbr hs[s] + hs[d]) + bias)
__device__ __forceinline__ void acc8(float* acc, uint4 u) {
    __half2* h = (__half2*)&u;
#pragma unroll
    for (int i = 0; i < 4; i++) {
        float2 f = __half22float2(h[i]);
        acc[2 * i] += f.x;
        acc[2 * i + 1] += f.y;
    }
}

__global__ __launch_bounds__(256)
void gcn_agg_k(const __half* __restrict__ hs, const float* __restrict__ bias,
               float* __restrict__ out, int n)
{
    int w = (int)(((long)blockIdx.x * blockDim.x + threadIdx.x) >> 5);
    int lane = threadIdx.x & 31;
    if (w >= n) return;
    const uint4* hv = (const uint4*)hs;   // 8 halfs per uint4; 32 per node row

    float acc[8];
#pragma unroll
    for (int i = 0; i < 8; i++) acc[i] = 0.f;
    acc8(acc, hv[(size_t)w * 32 + lane]);   // self term

    int e = g_off[w], end = g_off[w + 1];
    for (; e + 4 <= end; e += 4) {
        int s0 = g_csr[e], s1 = g_csr[e + 1], s2 = g_csr[e + 2], s3 = g_csr[e + 3];
        uint4 u0 = hv[(size_t)s0 * 32 + lane];
        uint4 u1 = hv[(size_t)s1 * 32 + lane];
        uint4 u2 = hv[(size_t)s2 * 32 + lane];
        uint4 u3 = hv[(size_t)s3 * 32 + lane];
        acc8(acc, u0); acc8(acc, u1); acc8(acc, u2); acc8(acc, u3);
    }
    for (; e < end; e++)
        acc8(acc, hv[(size_t)g_csr[e] * 32 + lane]);

    float di = g_dinv[w];
    const float4* bv = (const float4*)bias;
    float4 bb0 = bv[lane * 2], bb1 = bv[lane * 2 + 1];
    float4 o0, o1;
    o0.x = fmaxf(acc[0] * di + bb0.x, 0.f); o0.y = fmaxf(acc[1] * di + bb0.y, 0.f);
    o0.z = fmaxf(acc[2] * di + bb0.z, 0.f); o0.w = fmaxf(acc[3] * di + bb0.w, 0.f);
    o1.x = fmaxf(acc[4] * di + bb1.x, 0.f); o1.y = fmaxf(acc[5] * di + bb1.y, 0.f);
    o1.z = fmaxf(acc[6] * di + bb1.z, 0.f); o1.w = fmaxf(acc[7] * di + bb1.w, 0.f);
    float4* ov = (float4*)(out + (size_t)w * HID);
    ov[lane * 2] = o0;
    ov[lane * 2 + 1] = o1;
}

// ---------------- pooling ----------------
__global__ void pool_zero_k() {
    int i = blockIdx.x * blockDim.x + threadIdx.x;
    if (i < GMAX * HID) g_pooled[i] = 0.f;
    if (i < GMAX) g_cntf[i] = 0.f;
}
__global__ __launch_bounds__(256)
void pool_k(const float* __restrict__ x, const int* __restrict__ batch, int n) {
    int w = (int)(((long)blockIdx.x * blockDim.x + threadIdx.x) >> 5);
    int lane = threadIdx.x & 31;
    if (w >= n) return;
    int gidx = batch[w];
    if (lane == 0) atomicAdd(&g_cntf[gidx], 1.f);
    const float4* xs = (const float4*)(x + (size_t)w * HID);
    float* pd = g_pooled + (size_t)gidx * HID;
    int b = lane * 2;
    red_add_v4(pd + b * 4, xs[b]);
    red_add_v4(pd + b * 4 + 4, xs[b + 1]);
}
__global__ void pool_div_k() {
    int i = blockIdx.x * blockDim.x + threadIdx.x;
    if (i < GMAX * HID) g_pooled[i] /= fmaxf(g_cntf[i >> 8], 1.f);
}

// ---------------- head ----------------
__global__ __launch_bounds__(256)
void head1_k(const float* __restrict__ Wl1, const float* __restrict__ bl1) {
    __shared__ float sp[HID];
    int g = blockIdx.x, j = threadIdx.x;
    sp[j] = g_pooled[g * HID + j];
    __syncthreads();
    float acc = bl1[j];
#pragma unroll 8
    for (int k = 0; k < HID; k++) acc += sp[k] * Wl1[k * HID + j];
    g_head[g * HID + j] = fmaxf(acc, 0.f);
}
__global__ void head2_k(const float* __restrict__ Wl2, const float* __restrict__ bl2,
                        float* __restrict__ out) {
    int g = threadIdx.x;
    if (g >= GMAX) return;
    float l0 = bl2[0], l1 = bl2[1];
#pragma unroll 8
    for (int k = 0; k < HID; k++) {
        float v = g_head[g * HID + k];
        l0 += v * Wl2[k * 2];
        l1 += v * Wl2[k * 2 + 1];
    }
    float m = fmaxf(l0, l1);
    float lse = m + logf(expf(l0 - m) + expf(l1 - m));
    out[g * 2]     = l0 - lse;
    out[g * 2 + 1] = l1 - lse;
}

// ---------------- launch ----------------
extern "C" void kernel_launch(void* const* d_in, const int* in_sizes, int n_in,
                              void* d_out, int out_size)
{
    const float* content = (const float*)d_in[0];
    const float* bert    = (const float*)d_in[1];
    const float* profile = (const float*)d_in[2];
    const float* spacy   = (const float*)d_in[3];
    const int*   eidx    = (const int*)d_in[4];
    const int*   batch   = (const int*)d_in[5];
    const float* Wc  = (const float*)d_in[6],  *bc  = (const float*)d_in[7];
    const float* Wb  = (const float*)d_in[8],  *bb  = (const float*)d_in[9];
    const float* Wp  = (const float*)d_in[10], *bp  = (const float*)d_in[11];
    const float* Ws  = (const float*)d_in[12], *bs  = (const float*)d_in[13];
    const float* Wg1 = (const float*)d_in[14], *bg1 = (const float*)d_in[15];
    const float* Wg2 = (const float*)d_in[16], *bg2 = (const float*)d_in[17];
    const float* Wl1 = (const float*)d_in[18], *bl1 = (const float*)d_in[19];
    const float* Wl2 = (const float*)d_in[20], *bl2 = (const float*)d_in[21];

    const int N = in_sizes[5];
    const int E = in_sizes[4] / 2;
    const int* src = eidx;
    const int* dst = eidx + E;

    float *xcat, *abuf, *dinv;
    __half* hh;
    cudaGetSymbolAddress((void**)&xcat, g_xcat);
    cudaGetSymbolAddress((void**)&abuf, g_agg);
    cudaGetSymbolAddress((void**)&hh,   g_hh);
    cudaGetSymbolAddress((void**)&dinv, g_dinv);

    cudaFuncSetAttribute(gemm_tf32_k, cudaFuncAttributeMaxDynamicSharedMemorySize, GEMM_SMEM);

    const int NT = 256;
    const dim3 gg(2, (N + BM - 1) / BM);
    const int nb = (N + 1023) / 1024;

    // CSR + dinv
    zero_cnt_k<<<(N + NT - 1) / NT, NT>>>(N);
    hist_k<<<(E + NT - 1) / NT, NT>>>(dst, E);
    dinv_k<<<(N + NT - 1) / NT, NT>>>(N);
    scan1_k<<<nb, NT>>>(N);
    scan2_k<<<1, NT>>>(nb);
    scan3_k<<<(N + NT - 1) / NT, NT>>>(N, E);
    scatter_k<<<(E + NT - 1) / NT, NT>>>(src, dst, E);

    // branch linears -> xcat [N, 1024] (fp32 out, bias+relu)
    gemm_tf32_k<<<gg, NT, GEMM_SMEM>>>(content, Wc, bc, xcat, nullptr, nullptr, N, 310, H4, 0,   1);
    gemm_tf32_k<<<gg, NT, GEMM_SMEM>>>(bert,    Wb, bb, xcat, nullptr, nullptr, N, 768, H4, 256, 1);
    gemm_tf32_k<<<gg, NT, GEMM_SMEM>>>(profile, Wp, bp, xcat, nullptr, nullptr, N, 10,  H4, 512, 1);
    gemm_tf32_k<<<gg, NT, GEMM_SMEM>>>(spacy,   Ws, bs, xcat, nullptr, nullptr, N, 300, H4, 768, 1);

    // conv1: hh = (xcat @ Wg1) * dinv[row] (fp16) -> aggregate
    gemm_tf32_k<<<gg, NT, GEMM_SMEM>>>(xcat, Wg1, nullptr, nullptr, hh, dinv, N, H4, HID, 0, 0);
    gcn_agg_k<<<(N * 32 + NT - 1) / NT, NT>>>(hh, bg1, abuf, N);

    // conv2
    gemm_tf32_k<<<gg, NT, GEMM_SMEM>>>(abuf, Wg2, nullptr, nullptr, hh, dinv, N, HID, HID, 0, 0);
    gcn_agg_k<<<(N * 32 + NT - 1) / NT, NT>>>(hh, bg2, abuf, N);

    // global mean pool
    pool_zero_k<<<(GMAX * HID + NT - 1) / NT, NT>>>();
    pool_k<<<(N * 32 + NT - 1) / NT, NT>>>(abuf, batch, N);
    pool_div_k<<<(GMAX * HID + NT - 1) / NT, NT>>>();

    // head
    head1_k<<<GMAX, HID>>>(Wl1, bl1);
    head2_k<<<1, 64>>>(Wl2, bl2, (float*)d_out);
}